// round 1
// baseline (speedup 1.0000x reference)
#include <cuda_runtime.h>
#include <cuda_bf16.h>

#define NPTS      500000
#define C_IN      16
#define C_OUT     64
#define D_IN      208          // 16 + 3*2*32
#define GRID_H    256
#define GRID_W    256
#define NCELL     (GRID_H * GRID_W)
#define BLK_PTS   64
#define NBLK      ((NPTS + BLK_PTS - 1) / BLK_PTS)

// shared memory layout (float offsets)
#define OFF_W1    0                    // 208*64 = 13312
#define OFF_X     13312                // 208*68 = 14144 (X transposed [k][pt], stride 68)
#define OFF_W2    27456                // 64*64  = 4096
#define OFF_H     31552                // 64*68  = 4352  (H transposed [c][pt], stride 68)
#define OFF_B1    35904                // 64
#define OFF_G     35968                // 64
#define OFF_B     36032                // 64
#define OFF_B2    36096                // 64
#define OFF_POS   36160                // 64*3
#define OFF_FEAT  36352                // 64*16
#define OFF_FLAT  37376                // 64 (ints)
#define SMEM_FLOATS 37440
#define SMEM_BYTES  (SMEM_FLOATS * 4)

__device__ float g_counts[NCELL];

__global__ void zero_kernel(float* __restrict__ out) {
    int idx = blockIdx.x * blockDim.x + threadIdx.x;
    if (idx < C_OUT * NCELL) out[idx] = 0.0f;
    if (idx < NCELL) g_counts[idx] = 0.0f;
}

__global__ __launch_bounds__(256, 1)
void p2g_kernel(const float* __restrict__ pos,
                const float* __restrict__ feat,
                const float* __restrict__ W1,
                const float* __restrict__ b1,
                const float* __restrict__ lng,
                const float* __restrict__ lnb,
                const float* __restrict__ W2,
                const float* __restrict__ b2,
                const int*   __restrict__ ax1p,
                const int*   __restrict__ ax2p,
                float* __restrict__ out) {
    extern __shared__ float sm[];
    int* sFlat = (int*)&sm[OFF_FLAT];
    const int tid  = threadIdx.x;
    const int base = blockIdx.x * BLK_PTS;

    // ---- stage weights / biases / points ----
    {
        const float4* w1v = (const float4*)W1;
        float4* sw1v = (float4*)&sm[OFF_W1];
        for (int i = tid; i < (D_IN * C_OUT) / 4; i += 256) sw1v[i] = w1v[i];
        const float4* w2v = (const float4*)W2;
        float4* sw2v = (float4*)&sm[OFF_W2];
        for (int i = tid; i < (C_OUT * C_OUT) / 4; i += 256) sw2v[i] = w2v[i];
        if (tid < 64) {
            sm[OFF_B1 + tid] = b1[tid];
            sm[OFF_G  + tid] = lng[tid];
            sm[OFF_B  + tid] = lnb[tid];
            sm[OFF_B2 + tid] = b2[tid];
        }
        for (int i = tid; i < BLK_PTS * 3; i += 256) {
            int p = i / 3, d = i - 3 * p;
            int g = min(base + p, NPTS - 1);
            sm[OFF_POS + i] = pos[g * 3 + d];
        }
        for (int i = tid; i < BLK_PTS * C_IN; i += 256) {
            int p = i >> 4, c = i & 15;
            int g = min(base + p, NPTS - 1);
            sm[OFF_FEAT + i] = feat[g * C_IN + c];
        }
    }
    __syncthreads();

    // ---- build X (transposed [k][pt]) and flat indices ----
    for (int idx = tid; idx < D_IN * BLK_PTS; idx += 256) {
        int k = idx >> 6;          // 0..207
        int p = idx & 63;
        float v;
        if (k < C_IN) {
            v = sm[OFF_FEAT + p * C_IN + k];
        } else {
            int j = k - C_IN;
            int d = j >> 6;        // spatial dim 0..2
            int r = j & 63;
            int t = r >> 5;        // 0=sin, 1=cos
            int f = r & 31;        // frequency index
            // (pos/2) * 2^(f/32) * pi
            float freq = exp2f((float)f * 0.03125f) * 1.57079632679489662f;
            float arg  = sm[OFF_POS + p * 3 + d] * freq;
            v = t ? __cosf(arg) : __sinf(arg);
        }
        sm[OFF_X + k * 68 + p] = v;
    }
    if (tid < BLK_PTS) {
        int a1 = *ax1p, a2 = *ax2p;
        float n1 = fminf(fmaxf((sm[OFF_POS + tid * 3 + a1] + 1.0f) * 0.5f, 0.0f), 1.0f);
        float n2 = fminf(fmaxf((sm[OFF_POS + tid * 3 + a2] + 1.0f) * 0.5f, 0.0f), 1.0f);
        int i1 = min(max((int)floorf(n1 * (float)GRID_H), 0), GRID_H - 1);
        int i2 = min(max((int)floorf(n2 * (float)GRID_W), 0), GRID_W - 1);
        sFlat[tid] = i1 * GRID_W + i2;
    }
    __syncthreads();

    const int ptg = tid >> 4;      // 0..15 -> points 4*ptg..4*ptg+3
    const int chg = tid & 15;      // 0..15 -> channels 4*chg..4*chg+3

    // ---- GEMM1: h[64pts][64ch] = X @ W1 ----
    float acc[4][4];
#pragma unroll
    for (int i = 0; i < 4; ++i)
#pragma unroll
        for (int j = 0; j < 4; ++j) acc[i][j] = 0.0f;

#pragma unroll 4
    for (int k = 0; k < D_IN; ++k) {
        float4 xv = *(const float4*)&sm[OFF_X  + k * 68 + 4 * ptg];
        float4 wv = *(const float4*)&sm[OFF_W1 + k * 64 + 4 * chg];
        float xs[4] = {xv.x, xv.y, xv.z, xv.w};
        float ws[4] = {wv.x, wv.y, wv.z, wv.w};
#pragma unroll
        for (int i = 0; i < 4; ++i)
#pragma unroll
            for (int j = 0; j < 4; ++j) acc[i][j] += xs[i] * ws[j];
    }

    // write H transposed [c][pt] with bias
#pragma unroll
    for (int j = 0; j < 4; ++j) {
        float bb = sm[OFF_B1 + 4 * chg + j];
#pragma unroll
        for (int i = 0; i < 4; ++i)
            sm[OFF_H + (4 * chg + j) * 68 + 4 * ptg + i] = acc[i][j] + bb;
    }
    __syncthreads();

    // ---- LayerNorm + exact GELU (4 threads per point) ----
    {
        int p = tid >> 2;
        int q = tid & 3;
        float s = 0.0f, s2 = 0.0f;
#pragma unroll
        for (int c = 16 * q; c < 16 * q + 16; ++c) {
            float v = sm[OFF_H + c * 68 + p];
            s += v; s2 += v * v;
        }
        s  += __shfl_xor_sync(0xFFFFFFFF, s, 1);
        s  += __shfl_xor_sync(0xFFFFFFFF, s, 2);
        s2 += __shfl_xor_sync(0xFFFFFFFF, s2, 1);
        s2 += __shfl_xor_sync(0xFFFFFFFF, s2, 2);
        float mu   = s * (1.0f / 64.0f);
        float var  = s2 * (1.0f / 64.0f) - mu * mu;
        float rstd = rsqrtf(var + 1e-5f);
#pragma unroll
        for (int c = 16 * q; c < 16 * q + 16; ++c) {
            float v = sm[OFF_H + c * 68 + p];
            v = (v - mu) * rstd * sm[OFF_G + c] + sm[OFF_B + c];
            v = 0.5f * v * (1.0f + erff(v * 0.70710678118654752f));
            sm[OFF_H + c * 68 + p] = v;
        }
    }
    __syncthreads();

    // ---- GEMM2: feat_out = H @ W2 + b2 ----
    float acc2[4][4];
#pragma unroll
    for (int i = 0; i < 4; ++i)
#pragma unroll
        for (int j = 0; j < 4; ++j) acc2[i][j] = 0.0f;

#pragma unroll 4
    for (int k = 0; k < C_OUT; ++k) {
        float4 xv = *(const float4*)&sm[OFF_H  + k * 68 + 4 * ptg];
        float4 wv = *(const float4*)&sm[OFF_W2 + k * 64 + 4 * chg];
        float xs[4] = {xv.x, xv.y, xv.z, xv.w};
        float ws[4] = {wv.x, wv.y, wv.z, wv.w};
#pragma unroll
        for (int i = 0; i < 4; ++i)
#pragma unroll
            for (int j = 0; j < 4; ++j) acc2[i][j] += xs[i] * ws[j];
    }

    // ---- scatter-add into grid (out laid out [C][H*W]) ----
#pragma unroll
    for (int i = 0; i < 4; ++i) {
        int pl = 4 * ptg + i;
        int pg = base + pl;
        if (pg < NPTS) {
            int fl = sFlat[pl];
#pragma unroll
            for (int j = 0; j < 4; ++j) {
                int c = 4 * chg + j;
                atomicAdd(&out[c * NCELL + fl], acc2[i][j] + sm[OFF_B2 + c]);
            }
            if (chg == 0) atomicAdd(&g_counts[fl], 1.0f);
        }
    }
}

__global__ void finalize_kernel(float* __restrict__ out) {
    int idx = blockIdx.x * blockDim.x + threadIdx.x;
    if (idx < C_OUT * NCELL) {
        int cell = idx & (NCELL - 1);
        out[idx] *= 1.0f / fmaxf(g_counts[cell], 1.0f);
    }
}

extern "C" void kernel_launch(void* const* d_in, const int* in_sizes, int n_in,
                              void* d_out, int out_size) {
    const float* pos  = (const float*)d_in[0];
    const float* feat = (const float*)d_in[1];
    const float* W1   = (const float*)d_in[2];
    const float* b1   = (const float*)d_in[3];
    const float* lng  = (const float*)d_in[4];
    const float* lnb  = (const float*)d_in[5];
    const float* W2   = (const float*)d_in[6];
    const float* b2   = (const float*)d_in[7];
    const int*   ax1  = (const int*)d_in[8];
    const int*   ax2  = (const int*)d_in[9];
    float* out = (float*)d_out;

    cudaFuncSetAttribute(p2g_kernel, cudaFuncAttributeMaxDynamicSharedMemorySize, SMEM_BYTES);

    int zgrid = (C_OUT * NCELL + 255) / 256;
    zero_kernel<<<zgrid, 256>>>(out);
    p2g_kernel<<<NBLK, 256, SMEM_BYTES>>>(pos, feat, W1, b1, lng, lnb, W2, b2, ax1, ax2, out);
    finalize_kernel<<<zgrid, 256>>>(out);
}

// round 3
// speedup vs baseline: 1.6582x; 1.6582x over previous
#include <cuda_runtime.h>
#include <cuda_bf16.h>

#define NPTS    500000
#define C_OUT   64
#define D_IN    208
#define GRID_H  256
#define GRID_W  256
#define NCELL   (GRID_H * GRID_W)
#define BLK     256                      // points per CTA
#define NBLK    ((NPTS + BLK - 1) / BLK)
#define KC      52                       // K-chunk for X staging (4 * 52 = 208)
#define HP      264                      // padded point-stride for H

// shared memory offsets (in floats)
#define OW1 0            // 208*64 = 13312
#define OW2 13312        // 64*64  = 4096
#define OX  17408        // 52*256 = 13312
#define OH  30720        // 64*264 = 16896
#define OB1 47616
#define OG  47680
#define OB  47744
#define OB2 47808
#define OFQ 47872        // 32 freqs
#define OFL 47904        // 256 ints
#define SMF 48160
#define SMB (SMF * 4)

__device__ float g_accum[NCELL * C_OUT];   // cell-major scratch [cell][ch]
__device__ float g_counts[NCELL];

__device__ __forceinline__ unsigned long long pk2(float w) {
    unsigned long long r;
    asm("mov.b64 %0, {%1, %1};" : "=l"(r) : "f"(w));
    return r;
}
__device__ __forceinline__ void fma2(unsigned long long& d, unsigned long long a,
                                     unsigned long long b) {
    asm("fma.rn.f32x2 %0, %1, %2, %0;" : "+l"(d) : "l"(a), "l"(b));
}
__device__ __forceinline__ float2 up2(unsigned long long a) {
    float2 r;
    asm("mov.b64 {%0, %1}, %2;" : "=f"(r.x), "=f"(r.y) : "l"(a));
    return r;
}
__device__ __forceinline__ void red4(float* p, float a, float b, float c, float d) {
    asm volatile("red.global.add.v4.f32 [%0], {%1, %2, %3, %4};"
                 :: "l"(p), "f"(a), "f"(b), "f"(c), "f"(d) : "memory");
}

__global__ void zero_kernel() {
    int idx = blockIdx.x * blockDim.x + threadIdx.x;
    if (idx < NCELL * C_OUT) g_accum[idx] = 0.0f;
    if (idx < NCELL) g_counts[idx] = 0.0f;
}

__global__ __launch_bounds__(256, 1)
void p2g_kernel(const float* __restrict__ pos,
                const float* __restrict__ feat,
                const float* __restrict__ W1,
                const float* __restrict__ b1,
                const float* __restrict__ lng,
                const float* __restrict__ lnb,
                const float* __restrict__ W2,
                const float* __restrict__ b2,
                const int*   __restrict__ ax1p,
                const int*   __restrict__ ax2p) {
    extern __shared__ float sm[];
    int* sFlat = (int*)&sm[OFL];
    const int tid  = threadIdx.x;
    const int base = blockIdx.x * BLK;

    // ---- stage weights / biases / freq table ----
    {
        const float4* w1v = (const float4*)W1;
        float4* d1 = (float4*)&sm[OW1];
#pragma unroll
        for (int i = 0; i < 13; ++i) d1[tid + i * 256] = w1v[tid + i * 256];
        const float4* w2v = (const float4*)W2;
        float4* d2 = (float4*)&sm[OW2];
#pragma unroll
        for (int i = 0; i < 4; ++i) d2[tid + i * 256] = w2v[tid + i * 256];
        if (tid < 64) {
            sm[OB1 + tid] = b1[tid];
            sm[OG  + tid] = lng[tid];
            sm[OB  + tid] = lnb[tid];
            sm[OB2 + tid] = b2[tid];
        }
        if (tid < 32) sm[OFQ + tid] = exp2f((float)tid * 0.03125f) * 1.57079632679489662f;
    }

    // ---- per-thread point: pos + flat index (thread tid owns point tid) ----
    const int pg = min(base + tid, NPTS - 1);
    float pd[3];
    pd[0] = pos[pg * 3 + 0];
    pd[1] = pos[pg * 3 + 1];
    pd[2] = pos[pg * 3 + 2];
    {
        int a1 = *ax1p, a2 = *ax2p;
        float n1 = fminf(fmaxf((pd[a1] + 1.0f) * 0.5f, 0.0f), 1.0f);
        float n2 = fminf(fmaxf((pd[a2] + 1.0f) * 0.5f, 0.0f), 1.0f);
        int i1 = min(max((int)floorf(n1 * (float)GRID_H), 0), GRID_H - 1);
        int i2 = min(max((int)floorf(n2 * (float)GRID_W), 0), GRID_W - 1);
        sFlat[tid] = i1 * GRID_W + i2;
    }

    const int ptg = tid >> 3;   // 0..31 -> points ptg*8..+7
    const int chg = tid & 7;    // 0..7  -> channels chg*8..+7

    unsigned long long acc[4][8];
#pragma unroll
    for (int a = 0; a < 4; ++a)
#pragma unroll
        for (int b = 0; b < 8; ++b) acc[a][b] = 0ull;

    __syncthreads();

    // ================= GEMM1: chunked K =================
    for (int c = 0; c < 4; ++c) {
        const int k0 = c * KC;
        // build X chunk [KC][256], column = own point
#pragma unroll 1
        for (int i = 0; i < KC; ++i) {
            int k = k0 + i;
            float v;
            if (k < 16) {
                v = feat[pg * 16 + k];
            } else {
                int j = k - 16;
                float arg = pd[j >> 6] * sm[OFQ + (j & 31)];
                v = (j & 32) ? __cosf(arg) : __sinf(arg);
            }
            sm[OX + i * 256 + tid] = v;
        }
        __syncthreads();

#pragma unroll 4
        for (int i = 0; i < KC; ++i) {
            const float* xr = &sm[OX + i * 256 + ptg * 8];
            ulonglong2 xa = *(const ulonglong2*)xr;
            ulonglong2 xb = *(const ulonglong2*)(xr + 4);
            unsigned long long xp[4] = {xa.x, xa.y, xb.x, xb.y};
            const float* wr = &sm[OW1 + (k0 + i) * 64 + chg * 8];
            float4 w0 = *(const float4*)wr;
            float4 w1 = *(const float4*)(wr + 4);
            unsigned long long wb[8] = {pk2(w0.x), pk2(w0.y), pk2(w0.z), pk2(w0.w),
                                        pk2(w1.x), pk2(w1.y), pk2(w1.z), pk2(w1.w)};
#pragma unroll
            for (int a = 0; a < 4; ++a)
#pragma unroll
                for (int b = 0; b < 8; ++b) fma2(acc[a][b], xp[a], wb[b]);
        }
        __syncthreads();
    }

    // ---- write H = h + b1 (layout [ch][pt], stride HP), reset acc ----
#pragma unroll
    for (int b = 0; b < 8; ++b) {
        int ch = chg * 8 + b;
        float bb = sm[OB1 + ch];
        float2 v0 = up2(acc[0][b]), v1 = up2(acc[1][b]);
        float2 v2 = up2(acc[2][b]), v3 = up2(acc[3][b]);
        float4 o0 = {v0.x + bb, v0.y + bb, v1.x + bb, v1.y + bb};
        float4 o1 = {v2.x + bb, v2.y + bb, v3.x + bb, v3.y + bb};
        *(float4*)&sm[OH + ch * HP + ptg * 8]     = o0;
        *(float4*)&sm[OH + ch * HP + ptg * 8 + 4] = o1;
        acc[0][b] = acc[1][b] = acc[2][b] = acc[3][b] = 0ull;
    }
    __syncthreads();

    // ---- LayerNorm + exact GELU: thread tid owns point tid ----
    {
        float s = 0.0f, s2 = 0.0f;
#pragma unroll 8
        for (int cc = 0; cc < 64; ++cc) {
            float v = sm[OH + cc * HP + tid];
            s += v; s2 += v * v;
        }
        float mu   = s * (1.0f / 64.0f);
        float var  = s2 * (1.0f / 64.0f) - mu * mu;
        float rstd = rsqrtf(var + 1e-5f);
#pragma unroll 8
        for (int cc = 0; cc < 64; ++cc) {
            float v = sm[OH + cc * HP + tid];
            v = (v - mu) * rstd * sm[OG + cc] + sm[OB + cc];
            v = 0.5f * v * (1.0f + erff(v * 0.70710678118654752f));
            sm[OH + cc * HP + tid] = v;
        }
    }
    __syncthreads();

    // ================= GEMM2 =================
#pragma unroll 4
    for (int k = 0; k < 64; ++k) {
        const float* xr = &sm[OH + k * HP + ptg * 8];
        ulonglong2 xa = *(const ulonglong2*)xr;
        ulonglong2 xb = *(const ulonglong2*)(xr + 4);
        unsigned long long xp[4] = {xa.x, xa.y, xb.x, xb.y};
        const float* wr = &sm[OW2 + k * 64 + chg * 8];
        float4 w0 = *(const float4*)wr;
        float4 w1 = *(const float4*)(wr + 4);
        unsigned long long wb[8] = {pk2(w0.x), pk2(w0.y), pk2(w0.z), pk2(w0.w),
                                    pk2(w1.x), pk2(w1.y), pk2(w1.z), pk2(w1.w)};
#pragma unroll
        for (int a = 0; a < 4; ++a)
#pragma unroll
            for (int b = 0; b < 8; ++b) fma2(acc[a][b], xp[a], wb[b]);
    }

    // ---- scatter: vectorized red into cell-major scratch ----
    float bias[8];
#pragma unroll
    for (int b = 0; b < 8; ++b) bias[b] = sm[OB2 + chg * 8 + b];

#pragma unroll
    for (int pl = 0; pl < 8; ++pl) {
        int pG = base + ptg * 8 + pl;
        if (pG < NPTS) {
            int fl = sFlat[ptg * 8 + pl];
            float* dst = &g_accum[fl * 64 + chg * 8];
            int pr = pl >> 1;
            bool hi = pl & 1;
            float v[8];
#pragma unroll
            for (int b = 0; b < 8; ++b) {
                float2 t = up2(acc[pr][b]);
                v[b] = (hi ? t.y : t.x) + bias[b];
            }
            red4(dst,     v[0], v[1], v[2], v[3]);
            red4(dst + 4, v[4], v[5], v[6], v[7]);
            if (chg == 0) atomicAdd(&g_counts[fl], 1.0f);
        }
    }
}

// transpose [cell][ch] -> [ch][cell] with mean division
__global__ __launch_bounds__(256)
void finalize_kernel(float* __restrict__ out) {
    __shared__ float tile[64][65];
    __shared__ float cnt[64];
    const int tid = threadIdx.x;
    const int cell0 = blockIdx.x * 64;

#pragma unroll
    for (int it = 0; it < 16; ++it) {
        int lin = it * 256 + tid;
        int row = lin >> 6, col = lin & 63;
        tile[row][col] = g_accum[(cell0 + row) * 64 + col];
    }
    if (tid < 64) cnt[tid] = 1.0f / fmaxf(g_counts[cell0 + tid], 1.0f);
    __syncthreads();

#pragma unroll
    for (int it = 0; it < 16; ++it) {
        int lin = it * 256 + tid;
        int ch = lin >> 6, cl = lin & 63;
        out[ch * NCELL + cell0 + cl] = tile[cl][ch] * cnt[cl];
    }
}

extern "C" void kernel_launch(void* const* d_in, const int* in_sizes, int n_in,
                              void* d_out, int out_size) {
    const float* pos  = (const float*)d_in[0];
    const float* feat = (const float*)d_in[1];
    const float* W1   = (const float*)d_in[2];
    const float* b1   = (const float*)d_in[3];
    const float* lng  = (const float*)d_in[4];
    const float* lnb  = (const float*)d_in[5];
    const float* W2   = (const float*)d_in[6];
    const float* b2   = (const float*)d_in[7];
    const int*   ax1  = (const int*)d_in[8];
    const int*   ax2  = (const int*)d_in[9];
    float* out = (float*)d_out;

    cudaFuncSetAttribute(p2g_kernel, cudaFuncAttributeMaxDynamicSharedMemorySize, SMB);

    zero_kernel<<<(NCELL * C_OUT + 255) / 256, 256>>>();
    p2g_kernel<<<NBLK, 256, SMB>>>(pos, feat, W1, b1, lng, lnb, W2, b2, ax1, ax2);
    finalize_kernel<<<NCELL / 64, 256>>>(out);
}